// round 2
// baseline (speedup 1.0000x reference)
#include <cuda_runtime.h>

#define NQ 2048
#define NB 8192
#define DIM 32
#define QT 16            // queries per block (register/L2 reuse factor)
#define SJ 4             // j-dimension splits
#define JT (NB / SJ)     // 2048 j per block
#define THREADS 256
#define NWARP (THREADS / 32)

// Cross-block partials (device globals: allocation-free scratch)
__device__ float g_pk[SJ * NQ];
__device__ float g_pky[SJ * NQ];

typedef unsigned long long ull;

__device__ __forceinline__ ull pk2(float lo, float hi) {
    ull r; asm("mov.b64 %0, {%1, %2};" : "=l"(r) : "f"(lo), "f"(hi)); return r;
}
__device__ __forceinline__ void upk2(ull v, float& lo, float& hi) {
    asm("mov.b64 {%0, %1}, %2;" : "=f"(lo), "=f"(hi) : "l"(v));
}
// Packed f32x2 FMA/MUL (Blackwell sm_100+; 2 lanes of math per instruction)
__device__ __forceinline__ ull fma2(ull a, ull b, ull c) {
    ull d; asm("fma.rn.f32x2 %0, %1, %2, %3;" : "=l"(d) : "l"(a), "l"(b), "l"(c)); return d;
}
__device__ __forceinline__ ull mul2(ull a, ull b) {
    ull d; asm("mul.rn.f32x2 %0, %1, %2;" : "=l"(d) : "l"(a), "l"(b)); return d;
}
__device__ __forceinline__ float ex2_approx(float x) {
    float y; asm("ex2.approx.f32 %0, %1;" : "=f"(y) : "f"(x)); return y;
}
__device__ __forceinline__ float sqrt_approx(float x) {
    float y; asm("sqrt.approx.f32 %0, %1;" : "=f"(y) : "f"(x)); return y;
}

__global__ __launch_bounds__(THREADS)
void relnw_pass1(const float* __restrict__ xb,
                 const float* __restrict__ yb,
                 const float* __restrict__ xq,
                 const float* __restrict__ r,
                 const float* __restrict__ sigma,
                 const float* __restrict__ rscale,
                 const float* __restrict__ w)
{
    __shared__ ull   s_xq2[QT][DIM / 2];   // w-scaled queries, packed f32x2
    __shared__ float s_q2[QT];             // |xq*w|^2 per query
    __shared__ ull   s_w2[DIM / 2];        // packed weights
    __shared__ float s_rk[NWARP][QT];
    __shared__ float s_ry[NWARP][QT];

    const int tid = threadIdx.x;
    const int bq  = blockIdx.x % (NQ / QT);
    const int bj  = blockIdx.x / (NQ / QT);
    const int i0  = bq * QT;

    if (tid < DIM / 2)
        s_w2[tid] = pk2(w[2 * tid], w[2 * tid + 1]);

    // Stage QT*DIM query values: 256 threads = 16 queries * 16 f32x2 slots
    {
        const int i = tid / (DIM / 2);
        const int c = tid % (DIM / 2);
        float a = xq[(i0 + i) * DIM + 2 * c]     * w[2 * c];
        float b = xq[(i0 + i) * DIM + 2 * c + 1] * w[2 * c + 1];
        s_xq2[i][c] = pk2(a, b);
    }
    __syncthreads();

    if (tid < QT) {
        float s = 0.f;
        #pragma unroll
        for (int c = 0; c < DIM / 2; c++) {
            float a, b; upk2(s_xq2[tid][c], a, b);
            s = fmaf(a, a, s); s = fmaf(b, b, s);
        }
        s_q2[tid] = s;
    }
    __syncthreads();

    const float LOG2E = 1.4426950408889634f;
    const float c1 = -LOG2E / sigma[0];    // multiplies dist
    const float c2 =  LOG2E * rscale[0];   // multiplies r

    float sk[QT], sky[QT];
    #pragma unroll
    for (int i = 0; i < QT; i++) { sk[i] = 0.f; sky[i] = 0.f; }

    for (int jt = 0; jt < JT; jt += THREADS) {
        const int j = bj * JT + jt + tid;

        // Load xb row (128B, 8x LDG.128), scale by w, pack f32x2, compute |.|^2
        const ulonglong2* p = reinterpret_cast<const ulonglong2*>(xb + (size_t)j * DIM);
        ull xv[DIM / 2];
        #pragma unroll
        for (int c = 0; c < DIM / 4; c++) {
            ulonglong2 t = p[c];
            xv[2 * c] = t.x; xv[2 * c + 1] = t.y;
        }
        ull b2a = 0ull;
        #pragma unroll
        for (int c = 0; c < DIM / 2; c++) {
            xv[c] = mul2(xv[c], s_w2[c]);
            b2a   = fma2(xv[c], xv[c], b2a);
        }
        float blo, bhi; upk2(b2a, blo, bhi);
        const float b2 = blo + bhi;
        const float yj = yb[j];
        const float* rp = r + (size_t)i0 * NB + j;  // coalesced across lanes

        #pragma unroll
        for (int i = 0; i < QT; i++) {
            ull acc = 0ull;
            #pragma unroll
            for (int c = 0; c < DIM / 2; c++)
                acc = fma2(s_xq2[i][c], xv[c], acc);   // SMEM broadcast reads
            float lo, hi; upk2(acc, lo, hi);
            const float dot  = lo + hi;
            const float d2   = fmaf(-2.f, dot, s_q2[i] + b2);
            const float dist = sqrt_approx(fmaxf(d2, 0.f));
            const float rv   = rp[(size_t)i * NB];
            const float arg  = fmaf(dist, c1, rv * c2);
            const float kv   = ex2_approx(arg);        // exp(-d/sigma + s*r)
            sk[i]  += kv;
            sky[i]  = fmaf(kv, yj, sky[i]);
        }
    }

    // Reduce across the block (deterministic: shuffle tree + fixed-order SMEM sum)
    const int wid = tid >> 5, lane = tid & 31;
    #pragma unroll
    for (int i = 0; i < QT; i++) {
        float a = sk[i], b = sky[i];
        #pragma unroll
        for (int off = 16; off > 0; off >>= 1) {
            a += __shfl_down_sync(0xffffffffu, a, off);
            b += __shfl_down_sync(0xffffffffu, b, off);
        }
        if (lane == 0) { s_rk[wid][i] = a; s_ry[wid][i] = b; }
    }
    __syncthreads();

    if (tid < QT) {
        float a = 0.f, b = 0.f;
        #pragma unroll
        for (int ww = 0; ww < NWARP; ww++) { a += s_rk[ww][tid]; b += s_ry[ww][tid]; }
        g_pk [bj * NQ + i0 + tid] = a;
        g_pky[bj * NQ + i0 + tid] = b;
    }
}

__global__ void relnw_pass2(float* __restrict__ out)
{
    const int i = blockIdx.x * blockDim.x + threadIdx.x;
    if (i < NQ) {
        float a = 0.f, b = 0.f;
        #pragma unroll
        for (int s = 0; s < SJ; s++) { a += g_pk[s * NQ + i]; b += g_pky[s * NQ + i]; }
        out[i] = b / (a + 1e-8f);
    }
}

extern "C" void kernel_launch(void* const* d_in, const int* in_sizes, int n_in,
                              void* d_out, int out_size)
{
    const float* xb     = (const float*)d_in[0];  // x_backgnd (8192,32)
    const float* yb     = (const float*)d_in[1];  // y_backgnd (8192,)
    const float* xq     = (const float*)d_in[2];  // x_query   (2048,32)
    const float* r      = (const float*)d_in[3];  // r         (2048,8192)
    const float* sigma  = (const float*)d_in[4];  // (1,)
    const float* rscale = (const float*)d_in[5];  // (1,)
    const float* w      = (const float*)d_in[6];  // (32,)
    float* out = (float*)d_out;

    relnw_pass1<<<(NQ / QT) * SJ, THREADS>>>(xb, yb, xq, r, sigma, rscale, w);
    relnw_pass2<<<NQ / THREADS, THREADS>>>(out);
}

// round 5
// speedup vs baseline: 5.1039x; 5.1039x over previous
#include <cuda_runtime.h>

#define NQ 2048
#define NB 8192
#define DIM 32
#define QT 16              // queries per block
#define THREADS 256
#define JR 2               // j's per thread (register-resident xb rows)
#define JB (THREADS * JR)  // 512 j per block
#define NJB (NB / JB)      // 16 j-splits
#define NWARP (THREADS / 32)

// Cross-block partials (device globals: allocation-free scratch)
__device__ float g_pk [NJB * NQ];
__device__ float g_pky[NJB * NQ];

typedef unsigned long long ull;

__device__ __forceinline__ ull pk2(float lo, float hi) {
    ull r; asm("mov.b64 %0, {%1, %2};" : "=l"(r) : "f"(lo), "f"(hi)); return r;
}
__device__ __forceinline__ void upk2(ull v, float& lo, float& hi) {
    asm("mov.b64 {%0, %1}, %2;" : "=f"(lo), "=f"(hi) : "l"(v));
}
// Packed f32x2 FMA/MUL (Blackwell; only reachable via PTX)
__device__ __forceinline__ ull fma2(ull a, ull b, ull c) {
    ull d; asm("fma.rn.f32x2 %0, %1, %2, %3;" : "=l"(d) : "l"(a), "l"(b), "l"(c)); return d;
}
__device__ __forceinline__ ull mul2(ull a, ull b) {
    ull d; asm("mul.rn.f32x2 %0, %1, %2;" : "=l"(d) : "l"(a), "l"(b)); return d;
}
__device__ __forceinline__ float ex2_approx(float x) {
    float y; asm("ex2.approx.f32 %0, %1;" : "=f"(y) : "f"(x)); return y;
}
__device__ __forceinline__ float sqrt_approx(float x) {
    float y; asm("sqrt.approx.f32 %0, %1;" : "=f"(y) : "f"(x)); return y;
}

__global__ __launch_bounds__(THREADS, 1)
void relnw_pass1(const float* __restrict__ xb,
                 const float* __restrict__ yb,
                 const float* __restrict__ xq,
                 const float* __restrict__ r,
                 const float* __restrict__ sigma,
                 const float* __restrict__ rscale,
                 const float* __restrict__ w)
{
    __shared__ ull   s_a[DIM / 2][QT];   // s_a[c][i] = (xqw[i][2c], xqw[i][2c+1])
    __shared__ float s_q2[QT];
    __shared__ ull   s_w2[DIM / 2];
    __shared__ float s_rk[NWARP][QT];
    __shared__ float s_ry[NWARP][QT];

    const int tid = threadIdx.x;
    const int bq  = blockIdx.x % (NQ / QT);
    const int bj  = blockIdx.x / (NQ / QT);
    const int i0  = bq * QT;
    const int j0  = bj * JB + tid;         // this thread's two j's
    const int j1  = j0 + THREADS;

    if (tid < DIM / 2)
        s_w2[tid] = pk2(w[2 * tid], w[2 * tid + 1]);

    // Stage query fragment: 256 threads = 16 queries x 16 f32x2 slots
    {
        const int i = tid >> 4;
        const int c = tid & 15;
        float a = xq[(i0 + i) * DIM + 2 * c]     * w[2 * c];
        float b = xq[(i0 + i) * DIM + 2 * c + 1] * w[2 * c + 1];
        s_a[c][i] = pk2(a, b);
    }
    __syncthreads();

    if (tid < QT) {
        float s = 0.f;
        #pragma unroll
        for (int c = 0; c < DIM / 2; c++) {
            float a, b; upk2(s_a[c][tid], a, b);
            s = fmaf(a, a, s); s = fmaf(b, b, s);
        }
        s_q2[tid] = s;
    }

    // ---- prefetch r tile early: hides DRAM latency under the whole mainloop
    float rv[QT][JR];
    #pragma unroll
    for (int i = 0; i < QT; i++) {
        rv[i][0] = __ldg(r + (size_t)(i0 + i) * NB + j0);
        rv[i][1] = __ldg(r + (size_t)(i0 + i) * NB + j1);
    }
    const float yj0 = yb[j0];
    const float yj1 = yb[j1];

    // ---- load & w-scale this thread's two xb rows into registers
    ull   xv[JR][DIM / 2];
    float b2[JR];
    #pragma unroll
    for (int jr = 0; jr < JR; jr++) {
        const int j = (jr == 0) ? j0 : j1;
        const ulonglong2* p = reinterpret_cast<const ulonglong2*>(xb + (size_t)j * DIM);
        #pragma unroll
        for (int c = 0; c < DIM / 4; c++) {
            ulonglong2 t = p[c];
            xv[jr][2 * c] = t.x; xv[jr][2 * c + 1] = t.y;
        }
        ull a2 = 0ull;
        #pragma unroll
        for (int c = 0; c < DIM / 2; c++) {
            xv[jr][c] = mul2(xv[jr][c], s_w2[c]);
            a2 = fma2(xv[jr][c], xv[jr][c], a2);
        }
        float lo, hi; upk2(a2, lo, hi);
        b2[jr] = lo + hi;
    }

    // ---- mainloop: 16 k-steps, each = 16 broadcast LDS + 32 independent fma2
    ull acc[QT][JR];
    #pragma unroll
    for (int i = 0; i < QT; i++)
        #pragma unroll
        for (int jr = 0; jr < JR; jr++)
            acc[i][jr] = 0ull;

    #pragma unroll
    for (int c = 0; c < DIM / 2; c++) {
        ull af[QT];
        #pragma unroll
        for (int i = 0; i < QT; i++)
            af[i] = s_a[c][i];                    // warp-uniform broadcast
        #pragma unroll
        for (int i = 0; i < QT; i++) {
            acc[i][0] = fma2(af[i], xv[0][c], acc[i][0]);
            acc[i][1] = fma2(af[i], xv[1][c], acc[i][1]);
        }
    }

    const float LOG2E = 1.4426950408889634f;
    const float c1 = -LOG2E / sigma[0];
    const float c2 =  LOG2E * rscale[0];

    // ---- epilogue: finish 32 dots, kernel-eval, accumulate
    float sk[QT], sky[QT];
    #pragma unroll
    for (int i = 0; i < QT; i++) { sk[i] = 0.f; sky[i] = 0.f; }

    #pragma unroll
    for (int i = 0; i < QT; i++) {
        const float qb2 = s_q2[i];
        {
            float lo, hi; upk2(acc[i][0], lo, hi);
            const float d2   = fmaf(-2.f, lo + hi, qb2 + b2[0]);
            const float dist = sqrt_approx(fmaxf(d2, 0.f));
            const float kv   = ex2_approx(fmaf(dist, c1, rv[i][0] * c2));
            sk[i]  += kv;
            sky[i]  = fmaf(kv, yj0, sky[i]);
        }
        {
            float lo, hi; upk2(acc[i][1], lo, hi);
            const float d2   = fmaf(-2.f, lo + hi, qb2 + b2[1]);
            const float dist = sqrt_approx(fmaxf(d2, 0.f));
            const float kv   = ex2_approx(fmaf(dist, c1, rv[i][1] * c2));
            sk[i]  += kv;
            sky[i]  = fmaf(kv, yj1, sky[i]);
        }
    }

    // ---- deterministic block reduction (shuffle tree + fixed-order SMEM)
    const int wid = tid >> 5, lane = tid & 31;
    #pragma unroll
    for (int i = 0; i < QT; i++) {
        float a = sk[i], b = sky[i];
        #pragma unroll
        for (int off = 16; off > 0; off >>= 1) {
            a += __shfl_down_sync(0xffffffffu, a, off);
            b += __shfl_down_sync(0xffffffffu, b, off);
        }
        if (lane == 0) { s_rk[wid][i] = a; s_ry[wid][i] = b; }
    }
    __syncthreads();

    if (tid < QT) {
        float a = 0.f, b = 0.f;
        #pragma unroll
        for (int ww = 0; ww < NWARP; ww++) { a += s_rk[ww][tid]; b += s_ry[ww][tid]; }
        g_pk [bj * NQ + i0 + tid] = a;
        g_pky[bj * NQ + i0 + tid] = b;
    }
}

__global__ void relnw_pass2(float* __restrict__ out)
{
    const int i = blockIdx.x * blockDim.x + threadIdx.x;
    if (i < NQ) {
        float a = 0.f, b = 0.f;
        #pragma unroll
        for (int s = 0; s < NJB; s++) { a += g_pk[s * NQ + i]; b += g_pky[s * NQ + i]; }
        out[i] = b / (a + 1e-8f);
    }
}

extern "C" void kernel_launch(void* const* d_in, const int* in_sizes, int n_in,
                              void* d_out, int out_size)
{
    const float* xb     = (const float*)d_in[0];  // x_backgnd (8192,32)
    const float* yb     = (const float*)d_in[1];  // y_backgnd (8192,)
    const float* xq     = (const float*)d_in[2];  // x_query   (2048,32)
    const float* r      = (const float*)d_in[3];  // r         (2048,8192)
    const float* sigma  = (const float*)d_in[4];  // (1,)
    const float* rscale = (const float*)d_in[5];  // (1,)
    const float* w      = (const float*)d_in[6];  // (32,)
    float* out = (float*)d_out;

    relnw_pass1<<<(NQ / QT) * NJB, THREADS>>>(xb, yb, xq, r, sigma, rscale, w);
    relnw_pass2<<<NQ / THREADS, THREADS>>>(out);
}